// round 17
// baseline (speedup 1.0000x reference)
#include <cuda_runtime.h>
#include <cuda_fp16.h>
#include <cstdint>

#define NN 100000
#define EE 3200000
#define DD 128
#define BN_EPS 1e-5f
#define CAP 64                         // slots per node (deg ~ Poisson(32))
#define MAXOVF (1 << 18)               // overflow capacity (pairs)

#define ZERO_BLOCKS ((NN + 255) / 256)        // 391
#define H16_BLOCKS  (NN * DD / 8 / 256 + 1)   // 6251
#define WT_BLOCKS   (128 * 256 / 256)         // 128
#define PRE_BLOCKS  (ZERO_BLOCKS + H16_BLOCKS + WT_BLOCKS)
#define EDGE_BLOCKS (EE / 4 / 256)            // 3125

// ---- scratch (device globals) ----
__device__ int    g_count[NN];
__device__ int    g_slots[(size_t)NN * CAP];   // src indices, slot r = rank r
__device__ int    g_ovf[2 * MAXOVF];           // (dst, src) pairs for rank >= CAP
__device__ int    g_ovf_ctr;
__device__ __half g_h16[(size_t)NN * DD];
__device__ __half g_neigh16[(size_t)NN * DD];
__device__ __half g_rst16[(size_t)NN * DD];
__device__ float  g_z[(size_t)NN * DD];        // Z = h @ W_self (fp32)
__device__ __half g_Wt16[128 * 256];           // [n][k] fp16 W^T over [W_self; W_neigh]
__device__ float  g_colsum[DD];
__device__ float  g_colsumsq[DD];

// ================= helpers =================
__device__ __forceinline__ uint32_t smem_u32(const void* p) {
    uint32_t a;
    asm("{ .reg .u64 t; cvta.to.shared.u64 t, %1; cvt.u32.u64 %0, t; }" : "=r"(a) : "l"(p));
    return a;
}
__device__ __forceinline__ void cp16(uint32_t saddr, const void* gaddr, bool valid) {
    asm volatile("cp.async.cg.shared.global [%0], [%1], 16, %2;"
                 :: "r"(saddr), "l"(gaddr), "r"(valid ? 16u : 0u) : "memory");
}
#define CP_COMMIT() asm volatile("cp.async.commit_group;" ::: "memory")
#define CP_WAIT(N)  asm volatile("cp.async.wait_group %0;" :: "n"(N) : "memory")

__device__ __forceinline__ void mma16(float* d, uint32_t a0, uint32_t a1, uint32_t a2,
                                      uint32_t a3, uint32_t b0, uint32_t b1) {
    asm volatile(
        "mma.sync.aligned.m16n8k16.row.col.f32.f16.f16.f32 "
        "{%0,%1,%2,%3}, {%4,%5,%6,%7}, {%8,%9}, {%0,%1,%2,%3};"
        : "+f"(d[0]), "+f"(d[1]), "+f"(d[2]), "+f"(d[3])
        : "r"(a0), "r"(a1), "r"(a2), "r"(a3), "r"(b0), "r"(b1));
}
__device__ __forceinline__ void ldsm_x4(uint32_t& r0, uint32_t& r1, uint32_t& r2,
                                        uint32_t& r3, uint32_t addr) {
    asm volatile("ldmatrix.sync.aligned.m8n8.x4.shared.b16 {%0,%1,%2,%3}, [%4];"
                 : "=r"(r0), "=r"(r1), "=r"(r2), "=r"(r3) : "r"(addr));
}

// ---------------------------------------------------------------- phase 1: zero | h->fp16 | W^T fp16
__global__ void k_pre(const float* __restrict__ h,
                      const float* __restrict__ Ws,
                      const float* __restrict__ Wn) {
    int b = blockIdx.x;
    if (b < ZERO_BLOCKS) {
        int i = b * 256 + threadIdx.x;
        if (i < NN) g_count[i] = 0;
        if (i < DD) { g_colsum[i] = 0.f; g_colsumsq[i] = 0.f; }
        if (i == 0) g_ovf_ctr = 0;
    } else if (b < ZERO_BLOCKS + H16_BLOCKS) {
        int i = (b - ZERO_BLOCKS) * 256 + threadIdx.x;
        const int TOT = NN * DD / 8;
        if (i >= TOT) return;
        float4 a = ((const float4*)h)[2 * i];
        float4 bb = ((const float4*)h)[2 * i + 1];
        __half2 r[4];
        r[0] = __float22half2_rn(make_float2(a.x, a.y));
        r[1] = __float22half2_rn(make_float2(a.z, a.w));
        r[2] = __float22half2_rn(make_float2(bb.x, bb.y));
        r[3] = __float22half2_rn(make_float2(bb.z, bb.w));
        ((uint4*)g_h16)[i] = *(uint4*)r;
    } else {
        int i = (b - ZERO_BLOCKS - H16_BLOCKS) * 256 + threadIdx.x;
        if (i >= 128 * 256) return;
        int n = i >> 8, k = i & 255;
        float v = (k < 128) ? Ws[(size_t)k * DD + n] : Wn[(size_t)(k - 128) * DD + n];
        g_Wt16[i] = __float2half_rn(v);
    }
}

// ---------------------------------------------------------------- edge-slot build
__device__ __forceinline__ void place_edge(int d, int s) {
    int r = atomicAdd(&g_count[d], 1);
    if (r < CAP) {
        g_slots[(size_t)d * CAP + r] = s;
    } else {
        int idx = atomicAdd(&g_ovf_ctr, 1);
        if (idx < MAXOVF) { g_ovf[2 * idx] = d; g_ovf[2 * idx + 1] = s; }
    }
}
__global__ void k_edges(const int* __restrict__ dst, const int* __restrict__ src) {
    int e4 = blockIdx.x * blockDim.x + threadIdx.x;
    if (e4 >= EE / 4) return;
    int4 d = ((const int4*)dst)[e4];
    int4 s = ((const int4*)src)[e4];
    place_edge(d.x, s.x);
    place_edge(d.y, s.y);
    place_edge(d.z, s.z);
    place_edge(d.w, s.w);
}

// ---------------------------------------------------------------- segment mean (1 warp / node, fp16 gather)
__global__ void k_aggregate() {
    int gwarp = (blockIdx.x * blockDim.x + threadIdx.x) >> 5;
    if (gwarp >= NN) return;
    int lane = threadIdx.x & 31;
    int start = gwarp * CAP;
    int deg = g_count[gwarp];
    int main_n = (deg < CAP) ? deg : CAP;

    float accA[4] = {0, 0, 0, 0};
    float accB[4] = {0, 0, 0, 0};

    int i = 0;
    for (; i + 32 <= main_n; i += 32) {
        int s = g_slots[start + i + lane];
#pragma unroll
        for (int j = 0; j < 32; j += 2) {
            int s0 = __shfl_sync(0xffffffffu, s, j);
            int s1 = __shfl_sync(0xffffffffu, s, j + 1);
            uint2 u0 = *((const uint2*)(g_h16 + (size_t)s0 * DD) + lane);
            uint2 u1 = *((const uint2*)(g_h16 + (size_t)s1 * DD) + lane);
            {
                float2 f0 = __half22float2(*(__half2*)&u0.x);
                float2 f1 = __half22float2(*(__half2*)&u0.y);
                accA[0] += f0.x; accA[1] += f0.y; accA[2] += f1.x; accA[3] += f1.y;
            }
            {
                float2 f0 = __half22float2(*(__half2*)&u1.x);
                float2 f1 = __half22float2(*(__half2*)&u1.y);
                accB[0] += f0.x; accB[1] += f0.y; accB[2] += f1.x; accB[3] += f1.y;
            }
        }
    }
    {
        int rem = main_n - i;
        int s = (lane < rem) ? g_slots[start + i + lane] : 0;
        for (int j = 0; j < rem; j++) {
            int sj = __shfl_sync(0xffffffffu, s, j);
            uint2 u = *((const uint2*)(g_h16 + (size_t)sj * DD) + lane);
            float2 f0 = __half22float2(*(__half2*)&u.x);
            float2 f1 = __half22float2(*(__half2*)&u.y);
            accA[0] += f0.x; accA[1] += f0.y; accA[2] += f1.x; accA[3] += f1.y;
        }
    }
    if (deg > CAP) {
        int n = g_ovf_ctr;
        if (n > MAXOVF) n = MAXOVF;
        for (int o = 0; o < n; o++) {
            if (g_ovf[2 * o] == gwarp) {
                int sj = g_ovf[2 * o + 1];
                uint2 u = *((const uint2*)(g_h16 + (size_t)sj * DD) + lane);
                float2 f0 = __half22float2(*(__half2*)&u.x);
                float2 f1 = __half22float2(*(__half2*)&u.y);
                accA[0] += f0.x; accA[1] += f0.y; accA[2] += f1.x; accA[3] += f1.y;
            }
        }
    }
    float inv = 1.0f / fmaxf((float)deg, 1.0f);
    __half2 p0 = __float22half2_rn(make_float2((accA[0] + accB[0]) * inv,
                                               (accA[1] + accB[1]) * inv));
    __half2 p1 = __float22half2_rn(make_float2((accA[2] + accB[2]) * inv,
                                               (accA[3] + accB[3]) * inv));
    uint2 o;
    o.x = *(uint32_t*)&p0;
    o.y = *(uint32_t*)&p1;
    *((uint2*)(g_neigh16 + (size_t)gwarp * DD) + lane) = o;
}

// ---------------------------------------------------------------- GEMM halves (K=128 each)
// Block tile 128x128, 8 warps (2M x 4N), ldmatrix, 4-stage cp.async (full K prefetch).
#define STRD16 40
#define CH16 (128 * STRD16)            // halves per (A or B) stage

// common mainloop: A rows from `abase16` (half, row stride DD), B k-offset koff (0 or 128)
#define GEMM_MAIN(ASRC, KOFF)                                                            \
    int lane7 = lane & 7;                                                                \
    int aRow = ((lane >> 3) & 1) * 8 + lane7;                                            \
    int aK   = ((lane >> 4) & 1) * 8;                                                    \
    int bRow = ((lane >> 4) & 1) * 8 + lane7;                                            \
    int bK   = ((lane >> 3) & 1) * 8;                                                    \
    auto issue = [&](int kk, int st) {                                                   \
        uint32_t ab = sbA + (uint32_t)(st * CH16) * 2u;                                  \
        _Pragma("unroll")                                                                \
        for (int i = 0; i < 2; i++) {                                                    \
            int slot = tid + i * 256;                                                    \
            int row = slot >> 2, seg = slot & 3;                                         \
            int gm = m0 + row;                                                           \
            cp16(ab + row * (STRD16 * 2) + seg * 16,                                     \
                 ASRC + (size_t)gm * DD + kk * 32 + seg * 8, gm < NN);                   \
        }                                                                                \
        uint32_t bb = sbB + (uint32_t)(st * CH16) * 2u;                                  \
        _Pragma("unroll")                                                                \
        for (int i = 0; i < 2; i++) {                                                    \
            int slot = tid + i * 256;                                                    \
            int row = slot >> 2, seg = slot & 3;                                         \
            cp16(bb + row * (STRD16 * 2) + seg * 16,                                     \
                 g_Wt16 + (size_t)row * 256 + (KOFF) + kk * 32 + seg * 8, true);         \
        }                                                                                \
        CP_COMMIT();                                                                     \
    };                                                                                   \
    float acc[4][4][4];                                                                  \
    _Pragma("unroll")                                                                    \
    for (int a = 0; a < 4; a++)                                                          \
        _Pragma("unroll")                                                                \
        for (int b = 0; b < 4; b++)                                                      \
            _Pragma("unroll")                                                            \
            for (int c = 0; c < 4; c++) acc[a][b][c] = 0.f;                              \
    issue(0, 0);                                                                         \
    issue(1, 1);                                                                         \
    _Pragma("unroll")                                                                    \
    for (int kk = 0; kk < 4; kk++) {                                                     \
        if (kk < 2) issue(kk + 2, kk + 2);                                               \
        if (kk < 2)       { CP_WAIT(2); }                                                \
        else if (kk == 2) { CP_WAIT(1); }                                                \
        else              { CP_WAIT(0); }                                                \
        __syncthreads();                                                                 \
        uint32_t ab = sbA + (uint32_t)(kk * CH16) * 2u;                                  \
        uint32_t bb = sbB + (uint32_t)(kk * CH16) * 2u;                                  \
        _Pragma("unroll")                                                                \
        for (int ks = 0; ks < 2; ks++) {                                                 \
            int kb = ks * 16;                                                            \
            uint32_t bf[4][2];                                                           \
            _Pragma("unroll")                                                            \
            for (int pair = 0; pair < 2; pair++) {                                       \
                int nb = warpN * 32 + pair * 16;                                         \
                uint32_t addr = bb + (uint32_t)((nb + bRow) * STRD16 + kb + bK) * 2u;    \
                ldsm_x4(bf[2 * pair][0], bf[2 * pair][1],                                \
                        bf[2 * pair + 1][0], bf[2 * pair + 1][1], addr);                 \
            }                                                                            \
            _Pragma("unroll")                                                            \
            for (int mf = 0; mf < 4; mf++) {                                             \
                int m = warpM * 64 + mf * 16;                                            \
                uint32_t a0, a1, a2, a3;                                                 \
                uint32_t addr = ab + (uint32_t)((m + aRow) * STRD16 + kb + aK) * 2u;     \
                ldsm_x4(a0, a1, a2, a3, addr);                                           \
                _Pragma("unroll")                                                        \
                for (int nf = 0; nf < 4; nf++)                                           \
                    mma16(acc[mf][nf], a0, a1, a2, a3, bf[nf][0], bf[nf][1]);            \
            }                                                                            \
        }                                                                                \
    }

// Z = h16 @ W_self  (runs on side stream, overlapped)
__global__ __launch_bounds__(256, 2) void k_gemm_self() {
    extern __shared__ __half sm16[];
    uint32_t sbA = smem_u32(sm16), sbB = smem_u32(sm16 + 4 * CH16);
    int tid = threadIdx.x;
    int wid = tid >> 5, lane = tid & 31;
    int g = lane >> 2, t = lane & 3;
    int warpM = wid >> 2, warpN = wid & 3;
    int m0 = blockIdx.x * 128;

    GEMM_MAIN(g_h16, 0)

#pragma unroll
    for (int nf = 0; nf < 4; nf++) {
        int col = warpN * 32 + nf * 8 + 2 * t;
#pragma unroll
        for (int mf = 0; mf < 4; mf++) {
#pragma unroll
            for (int hh = 0; hh < 2; hh++) {
                int row = m0 + warpM * 64 + mf * 16 + g + hh * 8;
                if (row < NN) {
                    *(float2*)(g_z + (size_t)row * DD + col) =
                        make_float2(acc[mf][nf][hh * 2 + 0], acc[mf][nf][hh * 2 + 1]);
                }
            }
        }
    }
}

// rst = relu(Z + neigh16 @ W_neigh + bias); BN partials fused
__global__ __launch_bounds__(256, 2) void k_gemm_neigh(const float* __restrict__ bias) {
    extern __shared__ __half sm16[];
    uint32_t sbA = smem_u32(sm16), sbB = smem_u32(sm16 + 4 * CH16);
    float* cs = (float*)(sm16 + 8 * CH16);
    float* cq = cs + 128;
    int tid = threadIdx.x;
    int wid = tid >> 5, lane = tid & 31;
    int g = lane >> 2, t = lane & 3;
    int warpM = wid >> 2, warpN = wid & 3;
    int m0 = blockIdx.x * 128;

    if (tid < 128) { cs[tid] = 0.f; cq[tid] = 0.f; }

    GEMM_MAIN(g_neigh16, 128)

#pragma unroll
    for (int nf = 0; nf < 4; nf++) {
        int col = warpN * 32 + nf * 8 + 2 * t;
        float2 bv = *(const float2*)(bias + col);
        float s0 = 0.f, s1 = 0.f, q0 = 0.f, q1 = 0.f;
#pragma unroll
        for (int mf = 0; mf < 4; mf++) {
#pragma unroll
            for (int hh = 0; hh < 2; hh++) {
                int row = m0 + warpM * 64 + mf * 16 + g + hh * 8;
                if (row < NN) {
                    float2 z = *(const float2*)(g_z + (size_t)row * DD + col);
                    float v0 = fmaxf(z.x + acc[mf][nf][hh * 2 + 0] + bv.x, 0.f);
                    float v1 = fmaxf(z.y + acc[mf][nf][hh * 2 + 1] + bv.y, 0.f);
                    __half2 p = __float22half2_rn(make_float2(v0, v1));
                    *(__half2*)(g_rst16 + (size_t)row * DD + col) = p;
                    s0 += v0; q0 += v0 * v0;
                    s1 += v1; q1 += v1 * v1;
                }
            }
        }
        atomicAdd(&cs[col], s0);     atomicAdd(&cs[col + 1], s1);
        atomicAdd(&cq[col], q0);     atomicAdd(&cq[col + 1], q1);
    }
    __syncthreads();
    if (tid < 128) {
        atomicAdd(&g_colsum[tid], cs[tid]);
        atomicAdd(&g_colsumsq[tid], cq[tid]);
    }
}

// ---------------------------------------------------------------- normalize + residual (BN fold inline)
__global__ __launch_bounds__(256) void k_final(const float* __restrict__ h,
                                               const float* __restrict__ gamma,
                                               const float* __restrict__ beta,
                                               float* __restrict__ out) {
    __shared__ float s_scale[DD];
    __shared__ float s_shift[DD];
    if (threadIdx.x < DD) {
        int j = threadIdx.x;
        float mean = g_colsum[j] / (float)NN;
        float var = g_colsumsq[j] / (float)NN - mean * mean;
        float rs = rsqrtf(var + BN_EPS);
        float sc = rs * gamma[j];
        s_scale[j] = sc;
        s_shift[j] = beta[j] - mean * sc;
    }
    __syncthreads();

    int i4 = blockIdx.x * blockDim.x + threadIdx.x;
    const int TOT = NN * DD / 4;
    if (i4 >= TOT) return;
    int c4 = i4 & 31;
    uint2 u = ((const uint2*)g_rst16)[i4];
    float2 r0 = __half22float2(*(__half2*)&u.x);
    float2 r1 = __half22float2(*(__half2*)&u.y);
    float4 hv = ((const float4*)h)[i4];
    float4 sc = *((const float4*)s_scale + c4);
    float4 sh = *((const float4*)s_shift + c4);
    float4 o;
    o.x = hv.x + r0.x * sc.x + sh.x;
    o.y = hv.y + r0.y * sc.y + sh.y;
    o.z = hv.z + r1.x * sc.z + sh.z;
    o.w = hv.w + r1.y * sc.w + sh.w;
    ((float4*)out)[i4] = o;
}

// ---------------------------------------------------------------- launch
extern "C" void kernel_launch(void* const* d_in, const int* in_sizes, int n_in,
                              void* d_out, int out_size) {
    const float* h     = (const float*)d_in[0];
    const int*   src   = (const int*)d_in[1];
    const int*   dst   = (const int*)d_in[2];
    const float* bias  = (const float*)d_in[5];
    const float* gamma = (const float*)d_in[6];
    const float* beta  = (const float*)d_in[7];
    const float* Ws    = (const float*)d_in[3];
    const float* Wn    = (const float*)d_in[4];
    float* out = (float*)d_out;

    const int GEMM_SMEM = 8 * CH16 * 2 + 256 * 4;   // 81920 + 1024

    static cudaStream_t s2 = nullptr;
    static cudaEvent_t evFork = nullptr, evJoin = nullptr;
    if (!s2) {
        cudaFuncSetAttribute(k_gemm_self, cudaFuncAttributeMaxDynamicSharedMemorySize, GEMM_SMEM);
        cudaFuncSetAttribute(k_gemm_neigh, cudaFuncAttributeMaxDynamicSharedMemorySize, GEMM_SMEM);
        cudaStreamCreateWithFlags(&s2, cudaStreamNonBlocking);
        cudaEventCreateWithFlags(&evFork, cudaEventDisableTiming);
        cudaEventCreateWithFlags(&evJoin, cudaEventDisableTiming);
    }

    k_pre<<<PRE_BLOCKS, 256>>>(h, Ws, Wn);

    // fork: Z = h @ Ws on s2, overlapped with edge build + aggregate
    cudaEventRecord(evFork, 0);
    cudaStreamWaitEvent(s2, evFork, 0);
    k_gemm_self<<<(NN + 127) / 128, 256, GEMM_SMEM, s2>>>();
    cudaEventRecord(evJoin, s2);

    k_edges<<<EDGE_BLOCKS, 256>>>(dst, src);
    k_aggregate<<<(NN * 32 + 255) / 256, 256>>>();

    cudaStreamWaitEvent(0, evJoin, 0);
    k_gemm_neigh<<<(NN + 127) / 128, 256, GEMM_SMEM>>>(bias);
    k_final<<<(NN * DD / 4 + 255) / 256, 256>>>(h, gamma, beta, out);
}